// round 15
// baseline (speedup 1.0000x reference)
#include <cuda_runtime.h>
#include <cuda_fp16.h>
#include <cstdint>

// Problem constants
#define BATCH 2
#define SEQ   2048
#define CDIM  1024
#define HEADS 16
#define HDIM  64
#define QKV_N (3*CDIM)
#define MROWS (BATCH*SEQ)          // 4096
#define ATT_SCALE 0.125f           // 64^-0.5

#if defined(__CUDA_ARCH__) && defined(__CUDA_ARCH_FEAT_SM103_ALL)
#define HAS_TCGEN05 1
#else
#define HAS_TCGEN05 0
#endif

// ---------------------------------------------------------------------------
// Scratch (device globals)
// ---------------------------------------------------------------------------
__device__ __half g_q[BATCH*HEADS*SEQ*HDIM];
__device__ __half g_k[BATCH*HEADS*SEQ*HDIM];
__device__ __half g_v[BATCH*HEADS*SEQ*HDIM];
__device__ __half g_att[MROWS*CDIM];
__device__ __half g_xh[MROWS*CDIM];             // x fp16 [M, K]
__device__ __half g_wqkvh[CDIM*QKV_N];          // w_qkv fp16 [K, N]
__device__ __half g_wph[CDIM*CDIM];             // w_proj fp16 [K, N]
__device__ __half g_wqkvT[QKV_N*CDIM];          // w_qkv^T  [N, K]
__device__ __half g_wpT[CDIM*CDIM];             // w_proj^T [N, K]
__device__ int    g_ok;                          // tcgen05 sanity flag

// ---------------------------------------------------------------------------
// Common helpers
// ---------------------------------------------------------------------------
__device__ __forceinline__ void cp16(unsigned dst, const void* src) {
    asm volatile("cp.async.cg.shared.global [%0], [%1], 16;" :: "r"(dst), "l"(src));
}
#define CP_COMMIT() asm volatile("cp.async.commit_group;")
#define CP_WAIT(N)  asm volatile("cp.async.wait_group %0;" :: "n"(N))

__device__ __forceinline__ unsigned h2u(float a, float b) {
    half2 h = __floats2half2_rn(a, b);
    return *(unsigned*)&h;
}
__device__ __forceinline__ void mma16(float* c, const unsigned* a, const unsigned* b) {
    asm volatile(
        "mma.sync.aligned.m16n8k16.row.col.f32.f16.f16.f32 "
        "{%0,%1,%2,%3}, {%4,%5,%6,%7}, {%8,%9}, {%0,%1,%2,%3};"
        : "+f"(c[0]), "+f"(c[1]), "+f"(c[2]), "+f"(c[3])
        : "r"(a[0]), "r"(a[1]), "r"(a[2]), "r"(a[3]), "r"(b[0]), "r"(b[1]));
}
__device__ __forceinline__ void ldsm4(unsigned* d, unsigned addr) {
    asm volatile("ldmatrix.sync.aligned.m8n8.x4.shared.b16 {%0,%1,%2,%3}, [%4];"
                 : "=r"(d[0]), "=r"(d[1]), "=r"(d[2]), "=r"(d[3]) : "r"(addr));
}
__device__ __forceinline__ void ldsm4t(unsigned* d, unsigned addr) {
    asm volatile("ldmatrix.sync.aligned.m8n8.x4.trans.shared.b16 {%0,%1,%2,%3}, [%4];"
                 : "=r"(d[0]), "=r"(d[1]), "=r"(d[2]), "=r"(d[3]) : "r"(addr));
}

// ---------------------------------------------------------------------------
// Kernel 0a: convert x + weights to fp16
// ---------------------------------------------------------------------------
#define NX4 (MROWS*CDIM/4)
#define NQ4 (CDIM*QKV_N/4)
#define NP4 (CDIM*CDIM/4)

__global__ __launch_bounds__(256) void cvt3(const float4* __restrict__ x,
                                            const float4* __restrict__ wq,
                                            const float4* __restrict__ wp) {
    int i = blockIdx.x * blockDim.x + threadIdx.x;
    float4 v; uint2* dst;
    if (i < NX4)               { v = x[i];          dst = (uint2*)g_xh + i; }
    else if (i < NX4+NQ4)      { v = wq[i-NX4];     dst = (uint2*)g_wqkvh + (i-NX4); }
    else if (i < NX4+NQ4+NP4)  { v = wp[i-NX4-NQ4]; dst = (uint2*)g_wph + (i-NX4-NQ4); }
    else return;
    uint2 o;
    o.x = h2u(v.x, v.y); o.y = h2u(v.z, v.w);
    *dst = o;
}

// ---------------------------------------------------------------------------
// Kernel 0b: weight transpose + convert.  W[K,N] -> WT[N,K] fp16.
// ---------------------------------------------------------------------------
__global__ void cvt_t(const float* __restrict__ W, __half* __restrict__ WT, int N) {
    __shared__ float t[32][33];
    const int n0 = blockIdx.x * 32, k0 = blockIdx.y * 32;
    const int tx = threadIdx.x, ty = threadIdx.y;
#pragma unroll
    for (int i = 0; i < 4; i++)
        t[ty + i * 8][tx] = W[(size_t)(k0 + ty + i * 8) * N + n0 + tx];
    __syncthreads();
#pragma unroll
    for (int i = 0; i < 4; i++)
        WT[(size_t)(n0 + ty + i * 8) * CDIM + k0 + tx] = __float2half_rn(t[tx][ty + i * 8]);
}

// ---------------------------------------------------------------------------
// tcgen05 GEMM (diagnostic, self-checked): 128(M) x 64(N) tile, K=1024.
// Synchronous, st.shared staging, single buffer — example-faithful.
// ---------------------------------------------------------------------------
#define TCG_A    1024
#define TCG_B    (1024 + 16384)     // 17408
#define TCG_SMEM (TCG_B + 8192)     // 25600
#define SWZ(o) ((o) ^ (((o) >> 3) & 0x70))

#if HAS_TCGEN05
__device__ __forceinline__ bool elect1() {
    unsigned p;
    asm volatile("{\n .reg .pred p;\n elect.sync _|p, 0xFFFFFFFF;\n"
                 " selp.b32 %0, 1, 0, p;\n}" : "=r"(p));
    return p != 0;
}
#define MBAR_INIT(mbar, cnt) \
    asm volatile("mbarrier.init.shared.b64 [%0], %1;" \
                 :: "r"(mbar), "r"((unsigned)(cnt)) : "memory")
#define MBAR_WAIT(mbar, parity) do { \
    unsigned _m = (mbar), _p = (unsigned)(parity), _done; \
    asm volatile("{\n .reg .pred p;\n" \
        " mbarrier.try_wait.parity.acquire.cta.shared::cta.b64 p, [%1], %2;\n" \
        " selp.b32 %0, 1, 0, p;\n}" : "=r"(_done) : "r"(_m), "r"(_p) : "memory"); \
    if (!_done) { \
        asm volatile("{\n .reg .pred P1;\n" \
            "WAIT_LOOP_%=:\n" \
            " mbarrier.try_wait.parity.acquire.cta.shared::cta.b64 P1, [%0], %1, 0x989680;\n" \
            " @P1 bra.uni WAIT_DONE_%=;\n" \
            " bra.uni WAIT_LOOP_%=;\n" \
            "WAIT_DONE_%=:\n}" :: "r"(_m), "r"(_p) : "memory"); \
    } \
} while (0)

__device__ __forceinline__ void tc_mma_f16_ss(unsigned d_tmem, uint64_t a_desc,
                                              uint64_t b_desc, unsigned idesc,
                                              unsigned enable_d) {
    asm volatile(
        "{\n .reg .pred p;\n setp.ne.u32 p, %5, 0;\n"
        " tcgen05.mma.cta_group::1.kind::f16 [%0], %1, %2, %3, {%4, %4, %4, %4}, p;\n}"
        :: "r"(d_tmem), "l"(a_desc), "l"(b_desc), "r"(idesc), "r"(0u), "r"(enable_d)
        : "memory");
}
__device__ __forceinline__ uint64_t smem_desc(unsigned addr) {
    return (2ULL << 61) | (1ULL << 46) | (64ULL << 32) | (1ULL << 16)
         | ((uint64_t)(addr >> 4) & 0x3FFF);
}
// idesc: F32 acc, F16 a/b, N=64 (8<<17), M=128 (8<<24)
#define TC_IDESC ((1u << 4) | (8u << 17) | (8u << 24))
#endif

template<int NDIM, int EPI>
__global__ __launch_bounds__(256) void tc_gemm(const float* __restrict__ bias,
                                               float* __restrict__ out) {
#if HAS_TCGEN05
    extern __shared__ char smem[];
    const unsigned sb = (unsigned)__cvta_generic_to_shared(smem);
    const int tid = threadIdx.x, lane = tid & 31, wid = tid >> 5;
    const int row0 = blockIdx.y * 128, col0 = blockIdx.x * 64;

    const __half* A = (EPI == 0) ? g_xh    : g_att;
    const __half* B = (EPI == 0) ? g_wqkvT : g_wpT;

    if (tid == 0) MBAR_INIT(sb + 16, 1);
    if (wid == 0)
        asm volatile("tcgen05.alloc.cta_group::1.sync.aligned.shared::cta.b32 [%0], %1;"
                     :: "r"(sb), "r"(64u) : "memory");
    __syncthreads();
    unsigned tmem;
    asm volatile("ld.shared.b32 %0, [%1];" : "=r"(tmem) : "r"(sb));

    // staging maps
    const int ar = tid >> 1, acb = (tid & 1) * 64;   // A: 128 rows x 128B, 64B/thread
    const int br = tid >> 2, bcb = (tid & 3) * 32;   // B:  64 rows x 128B, 32B/thread
    const __half* aRow = A + (size_t)(row0 + ar) * CDIM + (acb >> 1);
    const __half* bRow = B + (size_t)(col0 + br) * CDIM + (bcb >> 1);

    const uint64_t ad0 = smem_desc(sb + TCG_A);
    const uint64_t bd0 = smem_desc(sb + TCG_B);

    const int NKT = CDIM / 64;   // 16
    for (int kt = 0; kt < NKT; ++kt) {
        // stage via plain stores (example-faithful)
#pragma unroll
        for (int j = 0; j < 4; ++j) {
            uint4 v = *(const uint4*)(aRow + kt * 64 + j * 8);
            *(uint4*)(smem + TCG_A + SWZ(ar * 128 + acb + j * 16)) = v;
        }
#pragma unroll
        for (int j = 0; j < 2; ++j) {
            uint4 v = *(const uint4*)(bRow + kt * 64 + j * 8);
            *(uint4*)(smem + TCG_B + SWZ(br * 128 + bcb + j * 16)) = v;
        }
        asm volatile("fence.proxy.async.shared::cta;" ::: "memory");
        __syncthreads();

        if (wid == 0 && elect1()) {
#pragma unroll
            for (int st = 0; st < 4; ++st)
                tc_mma_f16_ss(tmem, ad0 + st * 2, bd0 + st * 2, TC_IDESC,
                              (kt > 0) || (st > 0));
            asm volatile(
                "tcgen05.commit.cta_group::1.mbarrier::arrive::one.shared::cluster.b64 [%0];"
                :: "r"(sb + 16) : "memory");
        }
        MBAR_WAIT(sb + 16, kt & 1);
        __syncthreads();
    }
    asm volatile("tcgen05.fence::after_thread_sync;" ::: "memory");

    // epilogue: warp w -> rows (w&3)*32, cols (w>>2)*32
    const int colG = (wid >> 2) * 32;
    unsigned d0[32];
    asm volatile("tcgen05.ld.sync.aligned.32x32b.x32.b32 "
        "{%0, %1, %2, %3, %4, %5, %6, %7, "
        " %8, %9, %10, %11, %12, %13, %14, %15, "
        " %16, %17, %18, %19, %20, %21, %22, %23, "
        " %24, %25, %26, %27, %28, %29, %30, %31}, [%32];"
        : "=r"(d0[0]),  "=r"(d0[1]),  "=r"(d0[2]),  "=r"(d0[3]),
          "=r"(d0[4]),  "=r"(d0[5]),  "=r"(d0[6]),  "=r"(d0[7]),
          "=r"(d0[8]),  "=r"(d0[9]),  "=r"(d0[10]), "=r"(d0[11]),
          "=r"(d0[12]), "=r"(d0[13]), "=r"(d0[14]), "=r"(d0[15]),
          "=r"(d0[16]), "=r"(d0[17]), "=r"(d0[18]), "=r"(d0[19]),
          "=r"(d0[20]), "=r"(d0[21]), "=r"(d0[22]), "=r"(d0[23]),
          "=r"(d0[24]), "=r"(d0[25]), "=r"(d0[26]), "=r"(d0[27]),
          "=r"(d0[28]), "=r"(d0[29]), "=r"(d0[30]), "=r"(d0[31])
        : "r"(tmem + colG));
    asm volatile("tcgen05.wait::ld.sync.aligned;" ::: "memory");

    const int m = row0 + (wid & 3) * 32 + lane;
    const int gb = col0 + colG;                 // 32-aligned
    if (EPI == 0) {
        const int sel = gb >> 10;
        const int rc  = gb & (CDIM - 1);
        const int h = rc >> 6, dbase = rc & 63;
        const int b = m >> 11, n = m & (SEQ - 1);
        __half* dst = (sel == 0) ? g_q : (sel == 1) ? g_k : g_v;
        dst += ((size_t)(b * HEADS + h) * SEQ + n) * HDIM + dbase;
        const float sc = (sel == 0) ? ATT_SCALE : 1.f;
#pragma unroll
        for (int c = 0; c < 32; c += 2)
            *(half2*)&dst[c] = __floats2half2_rn(
                __uint_as_float(d0[c]) * sc, __uint_as_float(d0[c + 1]) * sc);
    } else {
        float* dst = out + (size_t)m * CDIM + gb;
        const float* bp = bias + gb;
#pragma unroll
        for (int c = 0; c < 32; c += 4) {
            float4 v;
            v.x = __uint_as_float(d0[c])     + __ldg(bp + c);
            v.y = __uint_as_float(d0[c + 1]) + __ldg(bp + c + 1);
            v.z = __uint_as_float(d0[c + 2]) + __ldg(bp + c + 2);
            v.w = __uint_as_float(d0[c + 3]) + __ldg(bp + c + 3);
            *(float4*)&dst[c] = v;
        }
    }

    __syncthreads();
    if (wid == 0)
        asm volatile("tcgen05.dealloc.cta_group::1.sync.aligned.b32 %0, %1;"
                     :: "r"(tmem), "r"(64u));
#else
    (void)bias; (void)out;   // PTX pass: no-op; runtime check routes to fallback
#endif
}

// ---------------------------------------------------------------------------
// tc_check: verify 256 scattered q/k/v samples against direct fp32 dots.
// One block, 1024 threads (32 warps x 8 samples, warp-parallel dot).
// ---------------------------------------------------------------------------
__global__ __launch_bounds__(1024) void tc_check() {
    __shared__ int bad;
    if (threadIdx.x == 0) bad = 0;
    __syncthreads();
    const int warp = threadIdx.x >> 5, lane = threadIdx.x & 31;
#pragma unroll
    for (int i = 0; i < 8; ++i) {
        const int s = warp * 8 + i;
        const int m = (s * 37 + 11) & (MROWS - 1);
        const int c = (s * 53 + 29) % QKV_N;
        float sum = 0.f;
        for (int k = lane; k < CDIM; k += 32)
            sum += __half2float(g_xh[(size_t)m * CDIM + k]) *
                   __half2float(g_wqkvh[(size_t)k * QKV_N + c]);
        sum += __shfl_xor_sync(0xffffffffu, sum, 16);
        sum += __shfl_xor_sync(0xffffffffu, sum, 8);
        sum += __shfl_xor_sync(0xffffffffu, sum, 4);
        sum += __shfl_xor_sync(0xffffffffu, sum, 2);
        sum += __shfl_xor_sync(0xffffffffu, sum, 1);
        if (lane == 0) {
            const int sel = c >> 10, rc = c & (CDIM - 1);
            const int h = rc >> 6, d = rc & 63;
            const int b = m >> 11, n = m & (SEQ - 1);
            const size_t idx = ((size_t)(b * HEADS + h) * SEQ + n) * HDIM + d;
            const float ref = (sel == 0) ? sum * ATT_SCALE : sum;
            const float got = __half2float(sel == 0 ? g_q[idx]
                                          : sel == 1 ? g_k[idx] : g_v[idx]);
            if (fabsf(got - ref) / fmaxf(fabsf(ref), 0.5f) > 0.02f)
                atomicOr(&bad, 1);
        }
    }
    __syncthreads();
    if (threadIdx.x == 0) g_ok = (bad == 0) ? 1 : 0;
}

// ---------------------------------------------------------------------------
// Fallback GEMM (proven round-10 mma.sync), early-exits if tcgen05 succeeded.
// ---------------------------------------------------------------------------
#define GA_STRIDE 80
#define GB_STRIDE 272
#define GA_BYTES (128*GA_STRIDE)
#define GB_BYTES (32*GB_STRIDE)
#define G_STG    (GA_BYTES + GB_BYTES)
#define G_SMEM   (4*G_STG)                 // 75776

template<int NDIM, int EPI>
__global__ __launch_bounds__(256) void gemm_fb(const float* __restrict__ bias,
                                               float* __restrict__ out) {
    if (g_ok) return;
    extern __shared__ char smem[];
    const __half* A  = (EPI == 0) ? g_xh    : g_att;
    const __half* Bm = (EPI == 0) ? g_wqkvh : g_wph;

    const int tid  = threadIdx.x;
    const int lane = tid & 31, warp = tid >> 5;
    const int wm = warp >> 2, wn = warp & 3;
    const int row0 = blockIdx.y * 128, col0 = blockIdx.x * 128;
    const unsigned sb = (unsigned)__cvta_generic_to_shared(smem);

    const int arow = tid >> 1, acolh = (tid & 1) * 16;
    const int brow = tid >> 3, bcolh = (tid & 7) * 16;

    auto stage = [&](int it, int s) {
        const __half* aSrc = A + (size_t)(row0 + arow) * CDIM + it * 32 + acolh;
        unsigned aDst = sb + s * G_STG + arow * GA_STRIDE + acolh * 2;
        cp16(aDst, aSrc); cp16(aDst + 16, aSrc + 8);
        const __half* bSrc = Bm + (size_t)(it * 32 + brow) * NDIM + col0 + bcolh;
        unsigned bDst = sb + s * G_STG + GA_BYTES + brow * GB_STRIDE + bcolh * 2;
        cp16(bDst, bSrc); cp16(bDst + 16, bSrc + 8);
    };

    float c[4][4][4] = {};

    stage(0, 0); CP_COMMIT();
    stage(1, 1); CP_COMMIT();
    stage(2, 2); CP_COMMIT();

    const unsigned aBase = sb + (wm * 64 + (lane & 15)) * GA_STRIDE + (lane >> 4) * 16;
    const unsigned bBase = sb + GA_BYTES + (lane & 15) * GB_STRIDE
                         + wn * 64 + (lane >> 4) * 16;

    const int NK = CDIM / 32;
    for (int it = 0; it < NK; ++it) {
        CP_WAIT(2);
        __syncthreads();
        if (it + 3 < NK) stage(it + 3, (it + 3) & 3);
        CP_COMMIT();

        const unsigned so = (it & 3) * G_STG;
#pragma unroll
        for (int ks = 0; ks < 2; ++ks) {
            unsigned af[4][4], bf[4][2];
#pragma unroll
            for (int mt = 0; mt < 4; ++mt)
                ldsm4(af[mt], aBase + so + mt * (16 * GA_STRIDE) + ks * 32);
#pragma unroll
            for (int ntp = 0; ntp < 2; ++ntp) {
                unsigned d4[4];
                ldsm4t(d4, bBase + so + ks * (16 * GB_STRIDE) + ntp * 32);
                bf[2*ntp][0] = d4[0];   bf[2*ntp][1] = d4[1];
                bf[2*ntp+1][0] = d4[2]; bf[2*ntp+1][1] = d4[3];
            }
#pragma unroll
            for (int mt = 0; mt < 4; ++mt)
#pragma unroll
                for (int nt = 0; nt < 4; ++nt)
                    mma16(c[mt][nt], af[mt], bf[nt]);
        }
    }

    if (EPI == 0) {
        const int sel = col0 >> 10;
#pragma unroll
        for (int mt = 0; mt < 4; ++mt) {
            const int r = row0 + wm * 64 + mt * 16 + (lane >> 2);
#pragma unroll
            for (int nt = 0; nt < 4; ++nt) {
                const int cc = col0 + wn * 32 + nt * 8 + (lane & 3) * 2;
#pragma unroll
                for (int hf = 0; hf < 2; ++hf) {
                    const int rr = r + hf * 8;
                    const int b = rr >> 11, n = rr & (SEQ - 1);
                    const int rc = cc & (CDIM - 1);
                    const int h = rc >> 6, d = rc & 63;
                    const int idx = ((b * HEADS + h) * SEQ + n) * HDIM + d;
                    float v0 = c[mt][nt][hf * 2], v1 = c[mt][nt][hf * 2 + 1];
                    if (sel == 0)
                        *(half2*)&g_q[idx] = __floats2half2_rn(v0 * ATT_SCALE, v1 * ATT_SCALE);
                    else if (sel == 1)
                        *(half2*)&g_k[idx] = __floats2half2_rn(v0, v1);
                    else
                        *(half2*)&g_v[idx] = __floats2half2_rn(v0, v1);
                }
            }
        }
    } else {
#pragma unroll
        for (int mt = 0; mt < 4; ++mt) {
            const int r = row0 + wm * 64 + mt * 16 + (lane >> 2);
#pragma unroll
            for (int nt = 0; nt < 4; ++nt) {
                const int cc = col0 + wn * 32 + nt * 8 + (lane & 3) * 2;
                const float b0 = __ldg(&bias[cc]), b1 = __ldg(&bias[cc + 1]);
                out[r * CDIM + cc]           = c[mt][nt][0] + b0;
                out[r * CDIM + cc + 1]       = c[mt][nt][1] + b1;
                out[(r + 8) * CDIM + cc]     = c[mt][nt][2] + b0;
                out[(r + 8) * CDIM + cc + 1] = c[mt][nt][3] + b1;
            }
        }
    }
}

// ---------------------------------------------------------------------------
// FlashAttention-2 (mma.sync fp16) — proven round-10 kernel, unchanged.
// ---------------------------------------------------------------------------
#define AQ_OFF  0
#define AKV_OFF 18432
#define KV_HALF 9216
#define KV_STG  18432
#define AT_SMEM (AKV_OFF + 2*KV_STG)       // 55296
#define A_STRIDE 144

__global__ __launch_bounds__(256) void attn_fa2() {
    extern __shared__ char smem[];
    const int tid = threadIdx.x, lane = tid & 31, wm = tid >> 5;
    const int bh = blockIdx.y, q0 = blockIdx.x * 128;
    const __half* Qg = g_q + (size_t)(bh * SEQ + q0) * HDIM;
    const __half* Kg = g_k + (size_t)bh * SEQ * HDIM;
    const __half* Vg = g_v + (size_t)bh * SEQ * HDIM;
    const unsigned sb = (unsigned)__cvta_generic_to_shared(smem);

    {
        const int r = tid >> 1, ch = (tid & 1) * 32;
        const __half* src = Qg + r * HDIM + ch;
        unsigned dst = sb + AQ_OFF + r * A_STRIDE + ch * 2;
        cp16(dst, src);           cp16(dst + 16, src + 8);
        cp16(dst + 32, src + 16); cp16(dst + 48, src + 24);
    }
    const int ldr = tid >> 2, ldch = (tid & 3) * 16;
    auto stageKV = [&](int kt, int s) {
        const __half* ksrc = Kg + (size_t)(kt * 64 + ldr) * HDIM + ldch;
        const __half* vsrc = Vg + (size_t)(kt * 64 + ldr) * HDIM + ldch;
        unsigned kd = sb + AKV_OFF + s * KV_STG + ldr * A_STRIDE + ldch * 2;
        unsigned vd = kd + KV_HALF;
        cp16(kd, ksrc); cp16(kd + 16, ksrc + 8);
        cp16(vd, vsrc); cp16(vd + 16, vsrc + 8);
    };
    stageKV(0, 0);
    CP_COMMIT();
    CP_WAIT(0);
    __syncthreads();

    unsigned qa[4][4];
    const unsigned qBase = sb + AQ_OFF + (wm * 16 + (lane & 15)) * A_STRIDE + (lane >> 4) * 16;
#pragma unroll
    for (int ks = 0; ks < 4; ++ks) ldsm4(qa[ks], qBase + ks * 32);

    const unsigned kBase = sb + AKV_OFF + (lane & 15) * A_STRIDE + (lane >> 4) * 16;
    const unsigned vBase = kBase + KV_HALF;

    float o[8][4] = {};
    float m0 = -1e30f, m1 = -1e30f, l0 = 0.f, l1 = 0.f;

    const int NT = SEQ / 64;
    for (int it = 0; it < NT; ++it) {
        if (it > 0) { CP_WAIT(0); __syncthreads(); }
        if (it + 1 < NT) stageKV(it + 1, (it + 1) & 1);
        CP_COMMIT();
        const unsigned so = (it & 1) * KV_STG;

        float s[8][4] = {};
#pragma unroll
        for (int ks = 0; ks < 4; ++ks) {
            unsigned bf[8][2];
#pragma unroll
            for (int np = 0; np < 4; ++np) {
                unsigned d4[4];
                ldsm4(d4, kBase + so + np * (16 * A_STRIDE) + ks * 32);
                bf[2*np][0] = d4[0];   bf[2*np+1][0] = d4[1];
                bf[2*np][1] = d4[2];   bf[2*np+1][1] = d4[3];
            }
#pragma unroll
            for (int j = 0; j < 8; ++j) mma16(s[j], qa[ks], bf[j]);
        }

        float mx0 = -1e30f, mx1 = -1e30f;
#pragma unroll
        for (int j = 0; j < 8; ++j) {
            mx0 = fmaxf(mx0, fmaxf(s[j][0], s[j][1]));
            mx1 = fmaxf(mx1, fmaxf(s[j][2], s[j][3]));
        }
        mx0 = fmaxf(mx0, __shfl_xor_sync(0xffffffffu, mx0, 1));
        mx0 = fmaxf(mx0, __shfl_xor_sync(0xffffffffu, mx0, 2));
        mx1 = fmaxf(mx1, __shfl_xor_sync(0xffffffffu, mx1, 1));
        mx1 = fmaxf(mx1, __shfl_xor_sync(0xffffffffu, mx1, 2));
        const float nm0 = fmaxf(m0, mx0), nm1 = fmaxf(m1, mx1);
        const float f0 = __expf(m0 - nm0), f1 = __expf(m1 - nm1);
        m0 = nm0; m1 = nm1;

        float sum0 = 0.f, sum1 = 0.f;
        unsigned pa[4][4];
#pragma unroll
        for (int t = 0; t < 4; ++t) {
            float p00 = __expf(s[2*t][0]   - m0), p01 = __expf(s[2*t][1]   - m0);
            float p02 = __expf(s[2*t][2]   - m1), p03 = __expf(s[2*t][3]   - m1);
            float p10 = __expf(s[2*t+1][0] - m0), p11 = __expf(s[2*t+1][1] - m0);
            float p12 = __expf(s[2*t+1][2] - m1), p13 = __expf(s[2*t+1][3] - m1);
            sum0 += p00 + p01 + p10 + p11;
            sum1 += p02 + p03 + p12 + p13;
            pa[t][0] = h2u(p00, p01);
            pa[t][1] = h2u(p02, p03);
            pa[t][2] = h2u(p10, p11);
            pa[t][3] = h2u(p12, p13);
        }
        sum0 += __shfl_xor_sync(0xffffffffu, sum0, 1);
        sum0 += __shfl_xor_sync(0xffffffffu, sum0, 2);
        sum1 += __shfl_xor_sync(0xffffffffu, sum1, 1);
        sum1 += __shfl_xor_sync(0xffffffffu, sum1, 2);
        l0 = l0 * f0 + sum0;
        l1 = l1 * f1 + sum1;

#pragma unroll
        for (int j = 0; j < 8; ++j) {
            o[j][0] *= f0; o[j][1] *= f0; o[j][2] *= f1; o[j][3] *= f1;
        }
#pragma unroll
        for (int t = 0; t < 4; ++t) {
            unsigned bf[8][2];
#pragma unroll
            for (int np = 0; np < 4; ++np) {
                unsigned d4[4];
                ldsm4t(d4, vBase + so + t * (16 * A_STRIDE) + np * 32);
                bf[2*np][0] = d4[0];   bf[2*np][1] = d4[1];
                bf[2*np+1][0] = d4[2]; bf[2*np+1][1] = d4[3];
            }
#pragma unroll
            for (int j = 0; j < 8; ++j) mma16(o[j], pa[t], bf[j]);
        }
    }

    const int b = bh >> 4, h = bh & 15;
    const int r1 = wm * 16 + (lane >> 2);
    const float i0 = 1.f / l0, i1 = 1.f / l1;
    const int n1 = q0 + r1, n2 = n1 + 8;
#pragma unroll
    for (int j = 0; j < 8; ++j) {
        const int d = h * 64 + j * 8 + (lane & 3) * 2;
        *(half2*)&g_att[(size_t)(b * SEQ + n1) * CDIM + d] =
            __floats2half2_rn(o[j][0] * i0, o[j][1] * i0);
        *(half2*)&g_att[(size_t)(b * SEQ + n2) * CDIM + d] =
            __floats2half2_rn(o[j][2] * i1, o[j][3] * i1);
    }
}

// ---------------------------------------------------------------------------
extern "C" void kernel_launch(void* const* d_in, const int* in_sizes, int n_in,
                              void* d_out, int out_size) {
    const float* x      = (const float*)d_in[0];
    const float* w_qkv  = (const float*)d_in[1];
    const float* w_proj = (const float*)d_in[2];
    const float* b_proj = (const float*)d_in[3];
    float* out = (float*)d_out;
    (void)in_sizes; (void)n_in; (void)out_size;

    cudaFuncSetAttribute(tc_gemm<QKV_N, 0>, cudaFuncAttributeMaxDynamicSharedMemorySize, TCG_SMEM);
    cudaFuncSetAttribute(tc_gemm<CDIM, 1>,  cudaFuncAttributeMaxDynamicSharedMemorySize, TCG_SMEM);
    cudaFuncSetAttribute(gemm_fb<QKV_N, 0>, cudaFuncAttributeMaxDynamicSharedMemorySize, G_SMEM);
    cudaFuncSetAttribute(gemm_fb<CDIM, 1>,  cudaFuncAttributeMaxDynamicSharedMemorySize, G_SMEM);
    cudaFuncSetAttribute(attn_fa2,          cudaFuncAttributeMaxDynamicSharedMemorySize, AT_SMEM);

    const int ncvt = NX4 + NQ4 + NP4;
    cvt3<<<(ncvt + 255) / 256, 256>>>((const float4*)x, (const float4*)w_qkv,
                                      (const float4*)w_proj);
    cvt_t<<<dim3(QKV_N / 32, CDIM / 32), dim3(32, 8)>>>(w_qkv, g_wqkvT, QKV_N);
    cvt_t<<<dim3(CDIM / 32, CDIM / 32), dim3(32, 8)>>>(w_proj, g_wpT, CDIM);

    // tcgen05 attempt + runtime verification
    tc_gemm<QKV_N, 0><<<dim3(QKV_N / 64, MROWS / 128), 256, TCG_SMEM>>>(nullptr, nullptr);
    tc_check<<<1, 1024>>>();

    // fallback (early-exits when tcgen05 results verified)
    gemm_fb<QKV_N, 0><<<dim3(QKV_N / 128, MROWS / 128), 256, G_SMEM>>>(nullptr, nullptr);

    attn_fa2<<<dim3(SEQ / 128, BATCH * HEADS), 256, AT_SMEM>>>();

    tc_gemm<CDIM, 1><<<dim3(CDIM / 64, MROWS / 128), 256, TCG_SMEM>>>(b_proj, out);
    gemm_fb<CDIM, 1><<<dim3(CDIM / 128, MROWS / 128), 256, G_SMEM>>>(b_proj, out);
}

// round 16
// speedup vs baseline: 2.4943x; 2.4943x over previous
#include <cuda_runtime.h>
#include <cuda_fp16.h>
#include <cstdint>

// Problem constants
#define BATCH 2
#define SEQ   2048
#define CDIM  1024
#define HEADS 16
#define HDIM  64
#define QKV_N (3*CDIM)
#define MROWS (BATCH*SEQ)          // 4096
#define ATT_SCALE 0.125f           // 64^-0.5

// ---------------------------------------------------------------------------
// Scratch (device globals) — fp16
// ---------------------------------------------------------------------------
__device__ __half g_q[BATCH*HEADS*SEQ*HDIM];    // pre-scaled by ATT_SCALE
__device__ __half g_k[BATCH*HEADS*SEQ*HDIM];
__device__ __half g_v[BATCH*HEADS*SEQ*HDIM];
__device__ __half g_att[MROWS*CDIM];
__device__ __half g_xh[MROWS*CDIM];             // x fp16 [M, K]
__device__ __half g_wqkvh[CDIM*QKV_N];          // w_qkv fp16 [K, N]
__device__ __half g_wph[CDIM*CDIM];             // w_proj fp16 [K, N]

// ---------------------------------------------------------------------------
// Helpers
// ---------------------------------------------------------------------------
__device__ __forceinline__ void cp16(unsigned dst, const void* src) {
    asm volatile("cp.async.cg.shared.global [%0], [%1], 16;" :: "r"(dst), "l"(src));
}
#define CP_COMMIT() asm volatile("cp.async.commit_group;")
#define CP_WAIT(N)  asm volatile("cp.async.wait_group %0;" :: "n"(N))

__device__ __forceinline__ unsigned h2u(float a, float b) {
    half2 h = __floats2half2_rn(a, b);
    return *(unsigned*)&h;
}
__device__ __forceinline__ void mma16(float* c, const unsigned* a, const unsigned* b) {
    asm volatile(
        "mma.sync.aligned.m16n8k16.row.col.f32.f16.f16.f32 "
        "{%0,%1,%2,%3}, {%4,%5,%6,%7}, {%8,%9}, {%0,%1,%2,%3};"
        : "+f"(c[0]), "+f"(c[1]), "+f"(c[2]), "+f"(c[3])
        : "r"(a[0]), "r"(a[1]), "r"(a[2]), "r"(a[3]), "r"(b[0]), "r"(b[1]));
}
__device__ __forceinline__ void ldsm4(unsigned* d, unsigned addr) {
    asm volatile("ldmatrix.sync.aligned.m8n8.x4.shared.b16 {%0,%1,%2,%3}, [%4];"
                 : "=r"(d[0]), "=r"(d[1]), "=r"(d[2]), "=r"(d[3]) : "r"(addr));
}
__device__ __forceinline__ void ldsm4t(unsigned* d, unsigned addr) {
    asm volatile("ldmatrix.sync.aligned.m8n8.x4.trans.shared.b16 {%0,%1,%2,%3}, [%4];"
                 : "=r"(d[0]), "=r"(d[1]), "=r"(d[2]), "=r"(d[3]) : "r"(addr));
}

// ---------------------------------------------------------------------------
// Kernel 0: convert x + weights to fp16
// ---------------------------------------------------------------------------
#define NX4 (MROWS*CDIM/4)
#define NQ4 (CDIM*QKV_N/4)
#define NP4 (CDIM*CDIM/4)

__global__ __launch_bounds__(256) void cvt3(const float4* __restrict__ x,
                                            const float4* __restrict__ wq,
                                            const float4* __restrict__ wp) {
    int i = blockIdx.x * blockDim.x + threadIdx.x;
    float4 v; uint2* dst;
    if (i < NX4)               { v = x[i];          dst = (uint2*)g_xh + i; }
    else if (i < NX4+NQ4)      { v = wq[i-NX4];     dst = (uint2*)g_wqkvh + (i-NX4); }
    else if (i < NX4+NQ4+NP4)  { v = wp[i-NX4-NQ4]; dst = (uint2*)g_wph + (i-NX4-NQ4); }
    else return;
    uint2 o;
    o.x = h2u(v.x, v.y); o.y = h2u(v.z, v.w);
    *dst = o;
}

// ---------------------------------------------------------------------------
// QKV GEMM: 128x256 CTA tile, BK=32, 3-stage cp.async, 8 warps (2x4),
// warp tile 64x64 (4 mt x 8 nt).  Halved B-fragment redundancy vs 128x128.
// ---------------------------------------------------------------------------
#define BGA_STRIDE 80                       // 64B data + 16 pad
#define BGB_STRIDE 528                      // 512B data + 16 pad
#define BGA_BYTES (128*BGA_STRIDE)          // 10240
#define BGB_BYTES (32*BGB_STRIDE)           // 16896
#define BG_STG    (BGA_BYTES + BGB_BYTES)   // 27136
#define BG_SMEM   (3*BG_STG)                // 81408

__global__ __launch_bounds__(256, 1) void qkv_big() {
    extern __shared__ char smem[];
    const int tid = threadIdx.x, lane = tid & 31, warp = tid >> 5;
    const int wm = warp >> 2, wn = warp & 3;
    const int row0 = blockIdx.y * 128, col0 = blockIdx.x * 256;
    const unsigned sb = (unsigned)__cvta_generic_to_shared(smem);

    // staging: A 128 rows x 64B (2 thr/row, 32B each); B 32 rows x 512B (8 thr/row, 64B each)
    const int arow = tid >> 1, acolh = (tid & 1) * 16;   // halves
    const int brow = tid >> 3, bcolh = (tid & 7) * 32;   // halves

    auto stage = [&](int it, int s) {
        const __half* aSrc = g_xh + (size_t)(row0 + arow) * CDIM + it * 32 + acolh;
        unsigned aDst = sb + s * BG_STG + arow * BGA_STRIDE + acolh * 2;
        cp16(aDst, aSrc); cp16(aDst + 16, aSrc + 8);
        const __half* bSrc = g_wqkvh + (size_t)(it * 32 + brow) * QKV_N + col0 + bcolh;
        unsigned bDst = sb + s * BG_STG + BGA_BYTES + brow * BGB_STRIDE + bcolh * 2;
#pragma unroll
        for (int j = 0; j < 4; j++) cp16(bDst + j * 16, bSrc + j * 8);
    };

    float c[4][8][4] = {};

    stage(0, 0); CP_COMMIT();
    stage(1, 1); CP_COMMIT();

    const unsigned aBase = sb + (wm * 64 + (lane & 15)) * BGA_STRIDE + (lane >> 4) * 16;
    const unsigned bBase = sb + BGA_BYTES + (lane & 15) * BGB_STRIDE
                         + wn * 128 + (lane >> 4) * 16;

    const int NK = CDIM / 32;
    int sidx = 2;                     // stage slot for it+2
    for (int it = 0; it < NK; ++it) {
        CP_WAIT(1);
        __syncthreads();
        if (it + 2 < NK) stage(it + 2, sidx);
        CP_COMMIT();
        const unsigned so = ((it % 3)) * BG_STG;
        if (++sidx == 3) sidx = 0;

#pragma unroll
        for (int ks = 0; ks < 2; ++ks) {
            unsigned af[4][4], bf[8][2];
#pragma unroll
            for (int mt = 0; mt < 4; ++mt)
                ldsm4(af[mt], aBase + so + mt * (16 * BGA_STRIDE) + ks * 32);
#pragma unroll
            for (int ntp = 0; ntp < 4; ++ntp) {
                unsigned d4[4];
                ldsm4t(d4, bBase + so + ks * (16 * BGB_STRIDE) + ntp * 32);
                bf[2*ntp][0] = d4[0];   bf[2*ntp][1] = d4[1];
                bf[2*ntp+1][0] = d4[2]; bf[2*ntp+1][1] = d4[3];
            }
#pragma unroll
            for (int mt = 0; mt < 4; ++mt)
#pragma unroll
                for (int nt = 0; nt < 8; ++nt)
                    mma16(c[mt][nt], af[mt], bf[nt]);
        }
    }

    // QKV scatter epilogue
#pragma unroll
    for (int mt = 0; mt < 4; ++mt) {
        const int r = row0 + wm * 64 + mt * 16 + (lane >> 2);
#pragma unroll
        for (int nt = 0; nt < 8; ++nt) {
            const int cc = col0 + wn * 64 + nt * 8 + (lane & 3) * 2;
            const int sel = cc >> 10;
            const int rc  = cc & (CDIM - 1);
            const int h = rc >> 6, d = rc & 63;
#pragma unroll
            for (int hf = 0; hf < 2; ++hf) {
                const int rr = r + hf * 8;
                const int b = rr >> 11, n = rr & (SEQ - 1);
                const int idx = ((b * HEADS + h) * SEQ + n) * HDIM + d;
                float v0 = c[mt][nt][hf * 2], v1 = c[mt][nt][hf * 2 + 1];
                if (sel == 0)
                    *(half2*)&g_q[idx] = __floats2half2_rn(v0 * ATT_SCALE, v1 * ATT_SCALE);
                else if (sel == 1)
                    *(half2*)&g_k[idx] = __floats2half2_rn(v0, v1);
                else
                    *(half2*)&g_v[idx] = __floats2half2_rn(v0, v1);
            }
        }
    }
}

// ---------------------------------------------------------------------------
// Proj GEMM: proven round-10 config. 128x128, BK=32, 4-stage, warp 64x32.
// ---------------------------------------------------------------------------
#define GA_STRIDE 80
#define GB_STRIDE 272
#define GA_BYTES (128*GA_STRIDE)
#define GB_BYTES (32*GB_STRIDE)
#define G_STG    (GA_BYTES + GB_BYTES)
#define G_SMEM   (4*G_STG)                 // 75776

__global__ __launch_bounds__(256) void proj_h(const float* __restrict__ bias,
                                              float* __restrict__ out) {
    extern __shared__ char smem[];
    const int tid  = threadIdx.x;
    const int lane = tid & 31, warp = tid >> 5;
    const int wm = warp >> 2, wn = warp & 3;
    const int row0 = blockIdx.y * 128, col0 = blockIdx.x * 128;
    const unsigned sb = (unsigned)__cvta_generic_to_shared(smem);

    const int arow = tid >> 1, acolh = (tid & 1) * 16;
    const int brow = tid >> 3, bcolh = (tid & 7) * 16;

    auto stage = [&](int it, int s) {
        const __half* aSrc = g_att + (size_t)(row0 + arow) * CDIM + it * 32 + acolh;
        unsigned aDst = sb + s * G_STG + arow * GA_STRIDE + acolh * 2;
        cp16(aDst, aSrc); cp16(aDst + 16, aSrc + 8);
        const __half* bSrc = g_wph + (size_t)(it * 32 + brow) * CDIM + col0 + bcolh;
        unsigned bDst = sb + s * G_STG + GA_BYTES + brow * GB_STRIDE + bcolh * 2;
        cp16(bDst, bSrc); cp16(bDst + 16, bSrc + 8);
    };

    float c[4][4][4] = {};

    stage(0, 0); CP_COMMIT();
    stage(1, 1); CP_COMMIT();
    stage(2, 2); CP_COMMIT();

    const unsigned aBase = sb + (wm * 64 + (lane & 15)) * GA_STRIDE + (lane >> 4) * 16;
    const unsigned bBase = sb + GA_BYTES + (lane & 15) * GB_STRIDE
                         + wn * 64 + (lane >> 4) * 16;

    const int NK = CDIM / 32;
    for (int it = 0; it < NK; ++it) {
        CP_WAIT(2);
        __syncthreads();
        if (it + 3 < NK) stage(it + 3, (it + 3) & 3);
        CP_COMMIT();

        const unsigned so = (it & 3) * G_STG;
#pragma unroll
        for (int ks = 0; ks < 2; ++ks) {
            unsigned af[4][4], bf[4][2];
#pragma unroll
            for (int mt = 0; mt < 4; ++mt)
                ldsm4(af[mt], aBase + so + mt * (16 * GA_STRIDE) + ks * 32);
#pragma unroll
            for (int ntp = 0; ntp < 2; ++ntp) {
                unsigned d4[4];
                ldsm4t(d4, bBase + so + ks * (16 * GB_STRIDE) + ntp * 32);
                bf[2*ntp][0] = d4[0];   bf[2*ntp][1] = d4[1];
                bf[2*ntp+1][0] = d4[2]; bf[2*ntp+1][1] = d4[3];
            }
#pragma unroll
            for (int mt = 0; mt < 4; ++mt)
#pragma unroll
                for (int nt = 0; nt < 4; ++nt)
                    mma16(c[mt][nt], af[mt], bf[nt]);
        }
    }

#pragma unroll
    for (int mt = 0; mt < 4; ++mt) {
        const int r = row0 + wm * 64 + mt * 16 + (lane >> 2);
#pragma unroll
        for (int nt = 0; nt < 4; ++nt) {
            const int cc = col0 + wn * 32 + nt * 8 + (lane & 3) * 2;
            const float b0 = __ldg(&bias[cc]), b1 = __ldg(&bias[cc + 1]);
            out[r * CDIM + cc]           = c[mt][nt][0] + b0;
            out[r * CDIM + cc + 1]       = c[mt][nt][1] + b1;
            out[(r + 8) * CDIM + cc]     = c[mt][nt][2] + b0;
            out[(r + 8) * CDIM + cc + 1] = c[mt][nt][3] + b1;
        }
    }
}

// ---------------------------------------------------------------------------
// FlashAttention-2 (mma.sync fp16) — proven round-10 kernel, unchanged.
// ---------------------------------------------------------------------------
#define AQ_OFF  0
#define AKV_OFF 18432
#define KV_HALF 9216
#define KV_STG  18432
#define AT_SMEM (AKV_OFF + 2*KV_STG)       // 55296
#define A_STRIDE 144

__global__ __launch_bounds__(256) void attn_fa2() {
    extern __shared__ char smem[];
    const int tid = threadIdx.x, lane = tid & 31, wm = tid >> 5;
    const int bh = blockIdx.y, q0 = blockIdx.x * 128;
    const __half* Qg = g_q + (size_t)(bh * SEQ + q0) * HDIM;
    const __half* Kg = g_k + (size_t)bh * SEQ * HDIM;
    const __half* Vg = g_v + (size_t)bh * SEQ * HDIM;
    const unsigned sb = (unsigned)__cvta_generic_to_shared(smem);

    {
        const int r = tid >> 1, ch = (tid & 1) * 32;
        const __half* src = Qg + r * HDIM + ch;
        unsigned dst = sb + AQ_OFF + r * A_STRIDE + ch * 2;
        cp16(dst, src);           cp16(dst + 16, src + 8);
        cp16(dst + 32, src + 16); cp16(dst + 48, src + 24);
    }
    const int ldr = tid >> 2, ldch = (tid & 3) * 16;
    auto stageKV = [&](int kt, int s) {
        const __half* ksrc = Kg + (size_t)(kt * 64 + ldr) * HDIM + ldch;
        const __half* vsrc = Vg + (size_t)(kt * 64 + ldr) * HDIM + ldch;
        unsigned kd = sb + AKV_OFF + s * KV_STG + ldr * A_STRIDE + ldch * 2;
        unsigned vd = kd + KV_HALF;
        cp16(kd, ksrc); cp16(kd + 16, ksrc + 8);
        cp16(vd, vsrc); cp16(vd + 16, vsrc + 8);
    };
    stageKV(0, 0);
    CP_COMMIT();
    CP_WAIT(0);
    __syncthreads();

    unsigned qa[4][4];
    const unsigned qBase = sb + AQ_OFF + (wm * 16 + (lane & 15)) * A_STRIDE + (lane >> 4) * 16;
#pragma unroll
    for (int ks = 0; ks < 4; ++ks) ldsm4(qa[ks], qBase + ks * 32);

    const unsigned kBase = sb + AKV_OFF + (lane & 15) * A_STRIDE + (lane >> 4) * 16;
    const unsigned vBase = kBase + KV_HALF;

    float o[8][4] = {};
    float m0 = -1e30f, m1 = -1e30f, l0 = 0.f, l1 = 0.f;

    const int NT = SEQ / 64;
    for (int it = 0; it < NT; ++it) {
        if (it > 0) { CP_WAIT(0); __syncthreads(); }
        if (it + 1 < NT) stageKV(it + 1, (it + 1) & 1);
        CP_COMMIT();
        const unsigned so = (it & 1) * KV_STG;

        float s[8][4] = {};
#pragma unroll
        for (int ks = 0; ks < 4; ++ks) {
            unsigned bf[8][2];
#pragma unroll
            for (int np = 0; np < 4; ++np) {
                unsigned d4[4];
                ldsm4(d4, kBase + so + np * (16 * A_STRIDE) + ks * 32);
                bf[2*np][0] = d4[0];   bf[2*np+1][0] = d4[1];
                bf[2*np][1] = d4[2];   bf[2*np+1][1] = d4[3];
            }
#pragma unroll
            for (int j = 0; j < 8; ++j) mma16(s[j], qa[ks], bf[j]);
        }

        float mx0 = -1e30f, mx1 = -1e30f;
#pragma unroll
        for (int j = 0; j < 8; ++j) {
            mx0 = fmaxf(mx0, fmaxf(s[j][0], s[j][1]));
            mx1 = fmaxf(mx1, fmaxf(s[j][2], s[j][3]));
        }
        mx0 = fmaxf(mx0, __shfl_xor_sync(0xffffffffu, mx0, 1));
        mx0 = fmaxf(mx0, __shfl_xor_sync(0xffffffffu, mx0, 2));
        mx1 = fmaxf(mx1, __shfl_xor_sync(0xffffffffu, mx1, 1));
        mx1 = fmaxf(mx1, __shfl_xor_sync(0xffffffffu, mx1, 2));
        const float nm0 = fmaxf(m0, mx0), nm1 = fmaxf(m1, mx1);
        const float f0 = __expf(m0 - nm0), f1 = __expf(m1 - nm1);
        m0 = nm0; m1 = nm1;

        float sum0 = 0.f, sum1 = 0.f;
        unsigned pa[4][4];
#pragma unroll
        for (int t = 0; t < 4; ++t) {
            float p00 = __expf(s[2*t][0]   - m0), p01 = __expf(s[2*t][1]   - m0);
            float p02 = __expf(s[2*t][2]   - m1), p03 = __expf(s[2*t][3]   - m1);
            float p10 = __expf(s[2*t+1][0] - m0), p11 = __expf(s[2*t+1][1] - m0);
            float p12 = __expf(s[2*t+1][2] - m1), p13 = __expf(s[2*t+1][3] - m1);
            sum0 += p00 + p01 + p10 + p11;
            sum1 += p02 + p03 + p12 + p13;
            pa[t][0] = h2u(p00, p01);
            pa[t][1] = h2u(p02, p03);
            pa[t][2] = h2u(p10, p11);
            pa[t][3] = h2u(p12, p13);
        }
        sum0 += __shfl_xor_sync(0xffffffffu, sum0, 1);
        sum0 += __shfl_xor_sync(0xffffffffu, sum0, 2);
        sum1 += __shfl_xor_sync(0xffffffffu, sum1, 1);
        sum1 += __shfl_xor_sync(0xffffffffu, sum1, 2);
        l0 = l0 * f0 + sum0;
        l1 = l1 * f1 + sum1;

#pragma unroll
        for (int j = 0; j < 8; ++j) {
            o[j][0] *= f0; o[j][1] *= f0; o[j][2] *= f1; o[j][3] *= f1;
        }
#pragma unroll
        for (int t = 0; t < 4; ++t) {
            unsigned bf[8][2];
#pragma unroll
            for (int np = 0; np < 4; ++np) {
                unsigned d4[4];
                ldsm4t(d4, vBase + so + t * (16 * A_STRIDE) + np * 32);
                bf[2*np][0] = d4[0];   bf[2*np][1] = d4[1];
                bf[2*np+1][0] = d4[2]; bf[2*np+1][1] = d4[3];
            }
#pragma unroll
            for (int j = 0; j < 8; ++j) mma16(o[j], pa[t], bf[j]);
        }
    }

    const int b = bh >> 4, h = bh & 15;
    const int r1 = wm * 16 + (lane >> 2);
    const float i0 = 1.f / l0, i1 = 1.f / l1;
    const int n1 = q0 + r1, n2 = n1 + 8;
#pragma unroll
    for (int j = 0; j < 8; ++j) {
        const int d = h * 64 + j * 8 + (lane & 3) * 2;
        *(half2*)&g_att[(size_t)(b * SEQ + n1) * CDIM + d] =
            __floats2half2_rn(o[j][0] * i0, o[j][1] * i0);
        *(half2*)&g_att[(size_t)(b * SEQ + n2) * CDIM + d] =
            __floats2half2_rn(o[j][2] * i1, o[j][3] * i1);
    }
}

// ---------------------------------------------------------------------------
extern "C" void kernel_launch(void* const* d_in, const int* in_sizes, int n_in,
                              void* d_out, int out_size) {
    const float* x      = (const float*)d_in[0];
    const float* w_qkv  = (const float*)d_in[1];
    const float* w_proj = (const float*)d_in[2];
    const float* b_proj = (const float*)d_in[3];
    float* out = (float*)d_out;
    (void)in_sizes; (void)n_in; (void)out_size;

    cudaFuncSetAttribute(qkv_big,  cudaFuncAttributeMaxDynamicSharedMemorySize, BG_SMEM);
    cudaFuncSetAttribute(proj_h,   cudaFuncAttributeMaxDynamicSharedMemorySize, G_SMEM);
    cudaFuncSetAttribute(attn_fa2, cudaFuncAttributeMaxDynamicSharedMemorySize, AT_SMEM);

    const int ncvt = NX4 + NQ4 + NP4;
    cvt3<<<(ncvt + 255) / 256, 256>>>((const float4*)x, (const float4*)w_qkv,
                                      (const float4*)w_proj);

    qkv_big<<<dim3(QKV_N / 256, MROWS / 128), 256, BG_SMEM>>>();
    attn_fa2<<<dim3(SEQ / 128, BATCH * HEADS), 256, AT_SMEM>>>();
    proj_h<<<dim3(CDIM / 128, MROWS / 128), 256, G_SMEM>>>(b_proj, out);
}